// round 15
// baseline (speedup 1.0000x reference)
#include <cuda_runtime.h>
#include <cuda_bf16.h>

#define N_NODES  40000
#define N_EDGES  640000
#define HID      128
#define N_GRAPHS 256

typedef unsigned long long u64;

// ---------------- scratch (no allocation allowed) ----------------
__device__ float g_bufA[N_NODES * HID];   // gemm output (hw)
__device__ float g_bufB[N_NODES * HID];   // layer-1 output (pre-scaled by ns)
__device__ float g_bufC[N_NODES * HID];   // layer-2 output (post relu)
__device__ int   g_deg_out[N_NODES];
__device__ int   g_deg_in[N_NODES];
__device__ float g_ns[N_NODES];
__device__ float g_nd[N_NODES];
__device__ int   g_row_ptr[N_NODES + 1];
__device__ int   g_fill[N_NODES];
__device__ int   g_csr_src[N_EDGES];

// ---------------- f32x2 helpers ----------------
__device__ __forceinline__ u64 pack2(float lo, float hi) {
    u64 r; asm("mov.b64 %0, {%1, %2};" : "=l"(r) : "f"(lo), "f"(hi)); return r;
}
__device__ __forceinline__ void unpack2(float& lo, float& hi, u64 v) {
    asm("mov.b64 {%0, %1}, %2;" : "=f"(lo), "=f"(hi) : "l"(v));
}
__device__ __forceinline__ void fma2(u64& d, u64 a, u64 b) {
    asm("fma.rn.f32x2 %0, %1, %2, %0;" : "+l"(d) : "l"(a), "l"(b));
}

// ---------------- CSR build chain (side stream) ----------------
__global__ void zero_k() {
    int i = blockIdx.x * blockDim.x + threadIdx.x;
    if (i < N_NODES) { g_deg_out[i] = 0; g_deg_in[i] = 0; }
}

__global__ void degree_k(const int* __restrict__ src, const int* __restrict__ dst) {
    int e = blockIdx.x * blockDim.x + threadIdx.x;
    if (e < N_EDGES) {
        atomicAdd(&g_deg_out[src[e]], 1);
        atomicAdd(&g_deg_in[dst[e]], 1);
    }
}

__global__ void norms_k() {
    int i = blockIdx.x * blockDim.x + threadIdx.x;
    if (i < N_NODES) {
        g_ns[i] = rsqrtf(fmaxf((float)g_deg_out[i], 1.f));
        g_nd[i] = rsqrtf(fmaxf((float)g_deg_in[i], 1.f));
    }
}

#define SCAN_T 1024
#define SCAN_CH 40   // 1024*40 = 40960 >= N_NODES
__global__ __launch_bounds__(SCAN_T) void scan_k() {
    __shared__ int ssum[SCAN_T];
    int t = threadIdx.x;
    int base = t * SCAN_CH;
    int s = 0;
#pragma unroll 8
    for (int i = 0; i < SCAN_CH; i++) {
        int idx = base + i;
        if (idx < N_NODES) s += g_deg_in[idx];
    }
    ssum[t] = s;
    __syncthreads();
    for (int off = 1; off < SCAN_T; off <<= 1) {
        int v = ssum[t];
        int add = (t >= off) ? ssum[t - off] : 0;
        __syncthreads();
        ssum[t] = v + add;
        __syncthreads();
    }
    int run = (t == 0) ? 0 : ssum[t - 1];   // exclusive prefix
    for (int i = 0; i < SCAN_CH; i++) {
        int idx = base + i;
        if (idx < N_NODES) {
            g_row_ptr[idx] = run;
            g_fill[idx] = run;          // seed fill cursor == row_ptr
            run += g_deg_in[idx];
        }
    }
    if (t == SCAN_T - 1) g_row_ptr[N_NODES] = run;  // == N_EDGES
}

__global__ void fill_k(const int* __restrict__ src, const int* __restrict__ dst) {
    int e = blockIdx.x * blockDim.x + threadIdx.x;
    if (e < N_EDGES) {
        int pos = atomicAdd(&g_fill[dst[e]], 1);    // no dependent row_ptr load
        g_csr_src[pos] = src[e];
    }
}

// ---------------- pure GEMM: out[M,128] = in[M,128] @ W[128,128] ----------------
#define KC 16
__global__ __launch_bounds__(256) void gemm_k(
    const float* __restrict__ in, const float* __restrict__ W,
    float* __restrict__ out)
{
    __shared__ float sA[KC][HID + 4];
    __shared__ __align__(16) float sW[KC][HID];

    const int tid = threadIdx.x;
    const int tx = tid & 15;     // 0..15 -> columns
    const int ty = tid >> 4;     // 0..15 -> rows
    const int row0 = blockIdx.x * 128;

    u64 acc2[8][4];
#pragma unroll
    for (int i = 0; i < 8; i++)
#pragma unroll
        for (int j = 0; j < 4; j++) acc2[i][j] = 0ull;

    for (int k0 = 0; k0 < HID; k0 += KC) {
#pragma unroll
        for (int t = 0; t < 2; t++) {
            int l = tid + t * 256;        // 0..511
            int r = l >> 2;               // 0..127
            int kq = (l & 3) * 4;         // 0,4,8,12
            int grow = row0 + r;
            float4 v = make_float4(0.f, 0.f, 0.f, 0.f);
            if (grow < N_NODES)
                v = *(const float4*)&in[grow * HID + k0 + kq];
            sA[kq + 0][r] = v.x;
            sA[kq + 1][r] = v.y;
            sA[kq + 2][r] = v.z;
            sA[kq + 3][r] = v.w;
        }
#pragma unroll
        for (int t = 0; t < 2; t++) {
            int l = tid + t * 256;        // 0..511
            int kk = l >> 5;              // 0..15
            int n4 = (l & 31) * 4;        // 0..124
            *(float4*)&sW[kk][n4] = *(const float4*)&W[(k0 + kk) * HID + n4];
        }
        __syncthreads();

#pragma unroll
        for (int kk = 0; kk < KC; kk++) {
            float4 a0 = *(const float4*)&sA[kk][ty * 4];
            float4 a1 = *(const float4*)&sA[kk][ty * 4 + 64];
            const u64* wrow = (const u64*)&sW[kk][0];
            u64 w0 = wrow[tx * 2];
            u64 w1 = wrow[tx * 2 + 1];
            u64 w2 = wrow[tx * 2 + 32];
            u64 w3 = wrow[tx * 2 + 33];
            float a[8] = {a0.x, a0.y, a0.z, a0.w, a1.x, a1.y, a1.z, a1.w};
#pragma unroll
            for (int i = 0; i < 8; i++) {
                u64 aa = pack2(a[i], a[i]);
                fma2(acc2[i][0], aa, w0);
                fma2(acc2[i][1], aa, w1);
                fma2(acc2[i][2], aa, w2);
                fma2(acc2[i][3], aa, w3);
            }
        }
        __syncthreads();
    }

#pragma unroll
    for (int i = 0; i < 8; i++) {
        int r = row0 + ((i < 4) ? (ty * 4 + i) : (ty * 4 + 64 + i - 4));
        if (r >= N_NODES) continue;
        float4 c0, c1;
        unpack2(c0.x, c0.y, acc2[i][0]);
        unpack2(c0.z, c0.w, acc2[i][1]);
        unpack2(c1.x, c1.y, acc2[i][2]);
        unpack2(c1.z, c1.w, acc2[i][3]);
        *(float4*)&out[r * HID + tx * 4] = c0;
        *(float4*)&out[r * HID + tx * 4 + 64] = c1;
    }
}

// ---------------- gather with fused norm/bias/relu epilogue (one warp per node) ----
// L1=true : acc = sum ns[s]*hw[s];  out = relu(acc*nd[w] + b) * ns[w]
// L1=false: acc = sum hw[s];        out = relu(acc*nd[w] + b)
template<bool L1>
__global__ __launch_bounds__(256) void gather_t(
    const float* __restrict__ hw, const float* __restrict__ bias,
    float* __restrict__ out)
{
    int w = (blockIdx.x * blockDim.x + threadIdx.x) >> 5;
    int lane = threadIdx.x & 31;
    if (w >= N_NODES) return;
    int beg = g_row_ptr[w], end = g_row_ptr[w + 1];
    float4 acc = make_float4(0.f, 0.f, 0.f, 0.f);
    int i = beg;
    for (; i + 3 < end; i += 4) {
        int s0 = g_csr_src[i + 0];
        int s1 = g_csr_src[i + 1];
        int s2 = g_csr_src[i + 2];
        int s3 = g_csr_src[i + 3];
        float n0 = 1.f, n1 = 1.f, n2 = 1.f, n3 = 1.f;
        if (L1) { n0 = g_ns[s0]; n1 = g_ns[s1]; n2 = g_ns[s2]; n3 = g_ns[s3]; }
        float4 v0 = *(const float4*)&hw[s0 * HID + lane * 4];
        float4 v1 = *(const float4*)&hw[s1 * HID + lane * 4];
        float4 v2 = *(const float4*)&hw[s2 * HID + lane * 4];
        float4 v3 = *(const float4*)&hw[s3 * HID + lane * 4];
        if (L1) {
            acc.x += n0 * v0.x + n1 * v1.x + n2 * v2.x + n3 * v3.x;
            acc.y += n0 * v0.y + n1 * v1.y + n2 * v2.y + n3 * v3.y;
            acc.z += n0 * v0.z + n1 * v1.z + n2 * v2.z + n3 * v3.z;
            acc.w += n0 * v0.w + n1 * v1.w + n2 * v2.w + n3 * v3.w;
        } else {
            acc.x += (v0.x + v1.x) + (v2.x + v3.x);
            acc.y += (v0.y + v1.y) + (v2.y + v3.y);
            acc.z += (v0.z + v1.z) + (v2.z + v3.z);
            acc.w += (v0.w + v1.w) + (v2.w + v3.w);
        }
    }
    for (; i < end; i++) {
        int s = g_csr_src[i];
        float n = L1 ? g_ns[s] : 1.f;
        float4 v = *(const float4*)&hw[s * HID + lane * 4];
        acc.x += n * v.x; acc.y += n * v.y; acc.z += n * v.z; acc.w += n * v.w;
    }
    float nd = g_nd[w];
    float4 bv = *(const float4*)&bias[lane * 4];
    float4 r;
    r.x = fmaxf(acc.x * nd + bv.x, 0.f);
    r.y = fmaxf(acc.y * nd + bv.y, 0.f);
    r.z = fmaxf(acc.z * nd + bv.z, 0.f);
    r.w = fmaxf(acc.w * nd + bv.w, 0.f);
    if (L1) {
        float nsw = g_ns[w];
        r.x *= nsw; r.y *= nsw; r.z *= nsw; r.w *= nsw;
    }
    *(float4*)&out[w * HID + lane * 4] = r;
}

// ---------------- fused pool (plain mean) + MLP head ----------------
__global__ __launch_bounds__(128) void head_k(
    const float* __restrict__ h2, const int* __restrict__ gid,
    const float* __restrict__ Wc1, const float* __restrict__ bc1,
    const float* __restrict__ Wc2, const float* __restrict__ bc2,
    const float* __restrict__ Wc3, const float* __restrict__ bc3,
    float* __restrict__ out)
{
    int g = blockIdx.x;
    int j = threadIdx.x;
    __shared__ int sRange[2];
    __shared__ float sIn[HID];
    __shared__ float sMid[HID];
    __shared__ float red[4];

    if (j < 2) {
        int target = g + j;
        int lo = 0, hi = N_NODES;
        while (lo < hi) {
            int mid = (lo + hi) >> 1;
            if (gid[mid] < target) lo = mid + 1; else hi = mid;
        }
        sRange[j] = lo;
    }
    __syncthreads();
    int beg = sRange[0], end = sRange[1];

    float acc = 0.f;
    for (int n = beg; n < end; n++) acc += h2[n * HID + j];
    float cnt = (float)(end - beg);
    sIn[j] = acc / fmaxf(cnt, 1.f);
    __syncthreads();

    float a = bc1[j];
#pragma unroll 4
    for (int k = 0; k < HID; k++) a += sIn[k] * Wc1[k * HID + j];
    sMid[j] = fmaxf(a, 0.f);
    __syncthreads();

    float b = bc2[j];
#pragma unroll 4
    for (int k = 0; k < HID; k++) b += sMid[k] * Wc2[k * HID + j];
    b = fmaxf(b, 0.f);

    float p = b * Wc3[j];
#pragma unroll
    for (int o = 16; o > 0; o >>= 1) p += __shfl_down_sync(0xffffffffu, p, o);
    if ((j & 31) == 0) red[j >> 5] = p;
    __syncthreads();
    if (j == 0) out[g] = red[0] + red[1] + red[2] + red[3] + bc3[0];
}

// ---------------- launch (fork-join: CSR build overlaps gemm1) ----------------
extern "C" void kernel_launch(void* const* d_in, const int* in_sizes, int n_in,
                              void* d_out, int out_size)
{
    const float* h   = (const float*)d_in[0];
    const int* src   = (const int*)d_in[1];
    const int* dst   = (const int*)d_in[2];
    const int* gid   = (const int*)d_in[3];
    const float* W1  = (const float*)d_in[4];
    const float* b1  = (const float*)d_in[5];
    const float* W2  = (const float*)d_in[6];
    const float* b2  = (const float*)d_in[7];
    const float* Wc1 = (const float*)d_in[8];
    const float* bc1 = (const float*)d_in[9];
    const float* Wc2 = (const float*)d_in[10];
    const float* bc2 = (const float*)d_in[11];
    const float* Wc3 = (const float*)d_in[12];
    const float* bc3 = (const float*)d_in[13];
    float* out = (float*)d_out;

    float *pA, *pB, *pC;
    cudaGetSymbolAddress((void**)&pA, g_bufA);
    cudaGetSymbolAddress((void**)&pB, g_bufB);
    cudaGetSymbolAddress((void**)&pC, g_bufC);

    // One-time infra (created on the correctness call, before graph capture;
    // identical work is launched on every call).
    static cudaStream_t s_side = nullptr;
    static cudaEvent_t ev_fork = nullptr, ev_join = nullptr;
    if (s_side == nullptr) {
        cudaStreamCreateWithFlags(&s_side, cudaStreamNonBlocking);
        cudaEventCreateWithFlags(&ev_fork, cudaEventDisableTiming);
        cudaEventCreateWithFlags(&ev_join, cudaEventDisableTiming);
    }

    const int gemm_blocks = (N_NODES + 127) / 128;          // 313
    const int gath_blocks = (N_NODES * 32 + 255) / 256;     // 5000

    // fork: CSR build chain on side stream
    cudaEventRecord(ev_fork, 0);
    cudaStreamWaitEvent(s_side, ev_fork, 0);
    zero_k  <<<(N_NODES + 255) / 256, 256, 0, s_side>>>();
    degree_k<<<(N_EDGES + 255) / 256, 256, 0, s_side>>>(src, dst);
    norms_k <<<(N_NODES + 255) / 256, 256, 0, s_side>>>();
    scan_k  <<<1, SCAN_T, 0, s_side>>>();
    fill_k  <<<(N_EDGES + 255) / 256, 256, 0, s_side>>>(src, dst);
    cudaEventRecord(ev_join, s_side);

    // main stream: pure gemm1 runs concurrently with CSR build
    gemm_k<<<gemm_blocks, 256>>>(h, W1, pA);

    // join, then the serial tail
    cudaStreamWaitEvent(0, ev_join, 0);
    gather_t<true> <<<gath_blocks, 256>>>(pA, b1, pB);   // bufB = relu(.)·ns
    gemm_k<<<gemm_blocks, 256>>>(pB, W2, pA);
    gather_t<false><<<gath_blocks, 256>>>(pA, b2, pC);   // bufC = h2
    head_k<<<N_GRAPHS, 128>>>(pC, gid, Wc1, bc1, Wc2, bc2, Wc3, bc3, out);
}

// round 17
// speedup vs baseline: 1.5208x; 1.5208x over previous
#include <cuda_runtime.h>
#include <cuda_fp16.h>

#define N_NODES  40000
#define N_EDGES  640000
#define HID      128
#define N_GRAPHS 256

#define SCAN_BLK   1024
#define SCAN_NBLK  40      // 40*1024 = 40960 >= N_NODES

typedef unsigned long long u64;

// ---------------- scratch (no allocation allowed) ----------------
__device__ __half g_hw[N_NODES * HID];    // gemm output (fp16)
__device__ float  g_bufB[N_NODES * HID];  // layer-1 output (pre-scaled by ns)
__device__ float  g_bufC[N_NODES * HID];  // layer-2 output (post relu)
__device__ int    g_deg_out[N_NODES];
__device__ int    g_deg_in[N_NODES];
__device__ float  g_ns[N_NODES];
__device__ float  g_nd[N_NODES];
__device__ int    g_row_ptr[N_NODES + 1];
__device__ int    g_fill[N_NODES];
__device__ int    g_csr_src[N_EDGES];
__device__ int    g_blk[SCAN_NBLK];
__device__ int    g_blkoff[SCAN_NBLK];

// ---------------- f32x2 helpers ----------------
__device__ __forceinline__ u64 pack2(float lo, float hi) {
    u64 r; asm("mov.b64 %0, {%1, %2};" : "=l"(r) : "f"(lo), "f"(hi)); return r;
}
__device__ __forceinline__ void unpack2(float& lo, float& hi, u64 v) {
    asm("mov.b64 {%0, %1}, %2;" : "=f"(lo), "=f"(hi) : "l"(v));
}
__device__ __forceinline__ void fma2(u64& d, u64 a, u64 b) {
    asm("fma.rn.f32x2 %0, %1, %2, %0;" : "+l"(d) : "l"(a), "l"(b));
}

// ---------------- fp16 bit-cast helpers ----------------
__device__ __forceinline__ unsigned h2_as_u32(__half2 h) {
    return *reinterpret_cast<unsigned*>(&h);
}
__device__ __forceinline__ __half2 u32_as_h2(unsigned u) {
    return *reinterpret_cast<__half2*>(&u);
}

// ---------------- CSR build chain (side stream) ----------------
__global__ void zero_k() {
    int i = blockIdx.x * blockDim.x + threadIdx.x;
    if (i < N_NODES) { g_deg_out[i] = 0; g_deg_in[i] = 0; }
}

__global__ void degree_k(const int* __restrict__ src, const int* __restrict__ dst) {
    int e = blockIdx.x * blockDim.x + threadIdx.x;
    if (e < N_EDGES) {
        atomicAdd(&g_deg_out[src[e]], 1);
        atomicAdd(&g_deg_in[dst[e]], 1);
    }
}

// stage 1: per-block exclusive scan of deg_in (1024 elements per block)
__global__ __launch_bounds__(SCAN_BLK) void scan1_k() {
    __shared__ int s[SCAN_BLK];
    int t = threadIdx.x;
    int n = blockIdx.x * SCAN_BLK + t;
    int v = (n < N_NODES) ? g_deg_in[n] : 0;
    s[t] = v;
    __syncthreads();
    // Hillis-Steele inclusive scan
    for (int off = 1; off < SCAN_BLK; off <<= 1) {
        int x = s[t];
        int add = (t >= off) ? s[t - off] : 0;
        __syncthreads();
        s[t] = x + add;
        __syncthreads();
    }
    if (n < N_NODES) g_row_ptr[n] = s[t] - v;   // exclusive, block-local
    if (t == SCAN_BLK - 1) g_blk[blockIdx.x] = s[t];
}

// stage 2: scan the 40 block totals (one tiny block)
__global__ void scan2_k() {
    __shared__ int s[64];
    int t = threadIdx.x;
    int v = (t < SCAN_NBLK) ? g_blk[t] : 0;
    s[t] = v;
    __syncthreads();
    for (int off = 1; off < 64; off <<= 1) {
        int x = s[t];
        int add = (t >= off) ? s[t - off] : 0;
        __syncthreads();
        s[t] = x + add;
        __syncthreads();
    }
    if (t < SCAN_NBLK) g_blkoff[t] = s[t] - v;  // exclusive
    if (t == 0) g_row_ptr[N_NODES] = N_EDGES;
}

// stage 3: add block offsets, seed fill cursor, compute norms
__global__ void scan3_k() {
    int i = blockIdx.x * blockDim.x + threadIdx.x;
    if (i < N_NODES) {
        int rp = g_row_ptr[i] + g_blkoff[i >> 10];
        g_row_ptr[i] = rp;
        g_fill[i] = rp;
        g_ns[i] = rsqrtf(fmaxf((float)g_deg_out[i], 1.f));
        g_nd[i] = rsqrtf(fmaxf((float)g_deg_in[i], 1.f));
    }
}

__global__ void fill_k(const int* __restrict__ src, const int* __restrict__ dst) {
    int e = blockIdx.x * blockDim.x + threadIdx.x;
    if (e < N_EDGES) {
        int pos = atomicAdd(&g_fill[dst[e]], 1);
        g_csr_src[pos] = src[e];
    }
}

// ---------------- GEMM: outh[M,128] = in[M,128] @ W[128,128], fp16 store ----------------
#define KC 16
__global__ __launch_bounds__(256) void gemm_k(
    const float* __restrict__ in, const float* __restrict__ W,
    __half* __restrict__ outh)
{
    __shared__ float sA[KC][HID + 4];
    __shared__ __align__(16) float sW[KC][HID];

    const int tid = threadIdx.x;
    const int tx = tid & 15;     // 0..15 -> columns
    const int ty = tid >> 4;     // 0..15 -> rows
    const int row0 = blockIdx.x * 128;

    u64 acc2[8][4];
#pragma unroll
    for (int i = 0; i < 8; i++)
#pragma unroll
        for (int j = 0; j < 4; j++) acc2[i][j] = 0ull;

    for (int k0 = 0; k0 < HID; k0 += KC) {
#pragma unroll
        for (int t = 0; t < 2; t++) {
            int l = tid + t * 256;        // 0..511
            int r = l >> 2;               // 0..127
            int kq = (l & 3) * 4;         // 0,4,8,12
            int grow = row0 + r;
            float4 v = make_float4(0.f, 0.f, 0.f, 0.f);
            if (grow < N_NODES)
                v = *(const float4*)&in[grow * HID + k0 + kq];
            sA[kq + 0][r] = v.x;
            sA[kq + 1][r] = v.y;
            sA[kq + 2][r] = v.z;
            sA[kq + 3][r] = v.w;
        }
#pragma unroll
        for (int t = 0; t < 2; t++) {
            int l = tid + t * 256;        // 0..511
            int kk = l >> 5;              // 0..15
            int n4 = (l & 31) * 4;        // 0..124
            *(float4*)&sW[kk][n4] = *(const float4*)&W[(k0 + kk) * HID + n4];
        }
        __syncthreads();

#pragma unroll
        for (int kk = 0; kk < KC; kk++) {
            float4 a0 = *(const float4*)&sA[kk][ty * 4];
            float4 a1 = *(const float4*)&sA[kk][ty * 4 + 64];
            const u64* wrow = (const u64*)&sW[kk][0];
            u64 w0 = wrow[tx * 2];
            u64 w1 = wrow[tx * 2 + 1];
            u64 w2 = wrow[tx * 2 + 32];
            u64 w3 = wrow[tx * 2 + 33];
            float a[8] = {a0.x, a0.y, a0.z, a0.w, a1.x, a1.y, a1.z, a1.w};
#pragma unroll
            for (int i = 0; i < 8; i++) {
                u64 aa = pack2(a[i], a[i]);
                fma2(acc2[i][0], aa, w0);
                fma2(acc2[i][1], aa, w1);
                fma2(acc2[i][2], aa, w2);
                fma2(acc2[i][3], aa, w3);
            }
        }
        __syncthreads();
    }

#pragma unroll
    for (int i = 0; i < 8; i++) {
        int r = row0 + ((i < 4) ? (ty * 4 + i) : (ty * 4 + 64 + i - 4));
        if (r >= N_NODES) continue;
        float4 c0, c1;
        unpack2(c0.x, c0.y, acc2[i][0]);
        unpack2(c0.z, c0.w, acc2[i][1]);
        unpack2(c1.x, c1.y, acc2[i][2]);
        unpack2(c1.z, c1.w, acc2[i][3]);
        uint2 o0 = make_uint2(h2_as_u32(__floats2half2_rn(c0.x, c0.y)),
                              h2_as_u32(__floats2half2_rn(c0.z, c0.w)));
        uint2 o1 = make_uint2(h2_as_u32(__floats2half2_rn(c1.x, c1.y)),
                              h2_as_u32(__floats2half2_rn(c1.z, c1.w)));
        *(uint2*)&outh[r * HID + tx * 4] = o0;
        *(uint2*)&outh[r * HID + tx * 4 + 64] = o1;
    }
}

// ---------------- gather (fp16 rows) with fused norm/bias/relu epilogue ----------------
// L1=true : acc = sum ns[s]*hw[s];  out = relu(acc*nd[w] + b) * ns[w]
// L1=false: acc = sum hw[s];        out = relu(acc*nd[w] + b)
template<bool L1>
__global__ __launch_bounds__(256) void gather_t(
    const __half* __restrict__ hw, const float* __restrict__ bias,
    float* __restrict__ out)
{
    int w = (blockIdx.x * blockDim.x + threadIdx.x) >> 5;
    int lane = threadIdx.x & 31;
    if (w >= N_NODES) return;
    int beg = g_row_ptr[w], end = g_row_ptr[w + 1];
    const uint2* hwp = (const uint2*)hw;   // 4 halves per uint2; 32 uint2 per row
    float4 acc = make_float4(0.f, 0.f, 0.f, 0.f);
    int i = beg;
    for (; i + 3 < end; i += 4) {
        int s0 = g_csr_src[i + 0];
        int s1 = g_csr_src[i + 1];
        int s2 = g_csr_src[i + 2];
        int s3 = g_csr_src[i + 3];
        float n0 = 1.f, n1 = 1.f, n2 = 1.f, n3 = 1.f;
        if (L1) { n0 = g_ns[s0]; n1 = g_ns[s1]; n2 = g_ns[s2]; n3 = g_ns[s3]; }
        uint2 u0 = hwp[s0 * 32 + lane];
        uint2 u1 = hwp[s1 * 32 + lane];
        uint2 u2 = hwp[s2 * 32 + lane];
        uint2 u3 = hwp[s3 * 32 + lane];
        float2 a0 = __half22float2(u32_as_h2(u0.x));
        float2 b0 = __half22float2(u32_as_h2(u0.y));
        float2 a1 = __half22float2(u32_as_h2(u1.x));
        float2 b1 = __half22float2(u32_as_h2(u1.y));
        float2 a2 = __half22float2(u32_as_h2(u2.x));
        float2 b2 = __half22float2(u32_as_h2(u2.y));
        float2 a3 = __half22float2(u32_as_h2(u3.x));
        float2 b3 = __half22float2(u32_as_h2(u3.y));
        acc.x += n0 * a0.x + n1 * a1.x + n2 * a2.x + n3 * a3.x;
        acc.y += n0 * a0.y + n1 * a1.y + n2 * a2.y + n3 * a3.y;
        acc.z += n0 * b0.x + n1 * b1.x + n2 * b2.x + n3 * b3.x;
        acc.w += n0 * b0.y + n1 * b1.y + n2 * b2.y + n3 * b3.y;
    }
    for (; i < end; i++) {
        int s = g_csr_src[i];
        float n = L1 ? g_ns[s] : 1.f;
        uint2 u = hwp[s * 32 + lane];
        float2 a = __half22float2(u32_as_h2(u.x));
        float2 b = __half22float2(u32_as_h2(u.y));
        acc.x += n * a.x; acc.y += n * a.y; acc.z += n * b.x; acc.w += n * b.y;
    }
    float nd = g_nd[w];
    float4 bv = *(const float4*)&bias[lane * 4];
    float4 r;
    r.x = fmaxf(acc.x * nd + bv.x, 0.f);
    r.y = fmaxf(acc.y * nd + bv.y, 0.f);
    r.z = fmaxf(acc.z * nd + bv.z, 0.f);
    r.w = fmaxf(acc.w * nd + bv.w, 0.f);
    if (L1) {
        float nsw = g_ns[w];
        r.x *= nsw; r.y *= nsw; r.z *= nsw; r.w *= nsw;
    }
    *(float4*)&out[w * HID + lane * 4] = r;
}

// ---------------- fused pool (plain mean) + MLP head ----------------
__global__ __launch_bounds__(128) void head_k(
    const float* __restrict__ h2, const int* __restrict__ gid,
    const float* __restrict__ Wc1, const float* __restrict__ bc1,
    const float* __restrict__ Wc2, const float* __restrict__ bc2,
    const float* __restrict__ Wc3, const float* __restrict__ bc3,
    float* __restrict__ out)
{
    int g = blockIdx.x;
    int j = threadIdx.x;
    __shared__ int sRange[2];
    __shared__ float sIn[HID];
    __shared__ float sMid[HID];
    __shared__ float red[4];

    if (j < 2) {
        int target = g + j;
        int lo = 0, hi = N_NODES;
        while (lo < hi) {
            int mid = (lo + hi) >> 1;
            if (gid[mid] < target) lo = mid + 1; else hi = mid;
        }
        sRange[j] = lo;
    }
    __syncthreads();
    int beg = sRange[0], end = sRange[1];

    float acc = 0.f;
    for (int n = beg; n < end; n++) acc += h2[n * HID + j];
    float cnt = (float)(end - beg);
    sIn[j] = acc / fmaxf(cnt, 1.f);
    __syncthreads();

    float a = bc1[j];
#pragma unroll 4
    for (int k = 0; k < HID; k++) a += sIn[k] * Wc1[k * HID + j];
    sMid[j] = fmaxf(a, 0.f);
    __syncthreads();

    float b = bc2[j];
#pragma unroll 4
    for (int k = 0; k < HID; k++) b += sMid[k] * Wc2[k * HID + j];
    b = fmaxf(b, 0.f);

    float p = b * Wc3[j];
#pragma unroll
    for (int o = 16; o > 0; o >>= 1) p += __shfl_down_sync(0xffffffffu, p, o);
    if ((j & 31) == 0) red[j >> 5] = p;
    __syncthreads();
    if (j == 0) out[g] = red[0] + red[1] + red[2] + red[3] + bc3[0];
}

// ---------------- launch (fork-join: CSR build overlaps gemm1) ----------------
extern "C" void kernel_launch(void* const* d_in, const int* in_sizes, int n_in,
                              void* d_out, int out_size)
{
    const float* h   = (const float*)d_in[0];
    const int* src   = (const int*)d_in[1];
    const int* dst   = (const int*)d_in[2];
    const int* gid   = (const int*)d_in[3];
    const float* W1  = (const float*)d_in[4];
    const float* b1  = (const float*)d_in[5];
    const float* W2  = (const float*)d_in[6];
    const float* b2  = (const float*)d_in[7];
    const float* Wc1 = (const float*)d_in[8];
    const float* bc1 = (const float*)d_in[9];
    const float* Wc2 = (const float*)d_in[10];
    const float* bc2 = (const float*)d_in[11];
    const float* Wc3 = (const float*)d_in[12];
    const float* bc3 = (const float*)d_in[13];
    float* out = (float*)d_out;

    __half* pHW;
    float *pB, *pC;
    cudaGetSymbolAddress((void**)&pHW, g_hw);
    cudaGetSymbolAddress((void**)&pB, g_bufB);
    cudaGetSymbolAddress((void**)&pC, g_bufC);

    static cudaStream_t s_side = nullptr;
    static cudaEvent_t ev_fork = nullptr, ev_join = nullptr;
    if (s_side == nullptr) {
        cudaStreamCreateWithFlags(&s_side, cudaStreamNonBlocking);
        cudaEventCreateWithFlags(&ev_fork, cudaEventDisableTiming);
        cudaEventCreateWithFlags(&ev_join, cudaEventDisableTiming);
    }

    const int gemm_blocks = (N_NODES + 127) / 128;          // 313
    const int gath_blocks = (N_NODES * 32 + 255) / 256;     // 5000

    // fork: CSR build chain on side stream
    cudaEventRecord(ev_fork, 0);
    cudaStreamWaitEvent(s_side, ev_fork, 0);
    zero_k  <<<(N_NODES + 255) / 256, 256, 0, s_side>>>();
    degree_k<<<(N_EDGES + 255) / 256, 256, 0, s_side>>>(src, dst);
    scan1_k <<<SCAN_NBLK, SCAN_BLK, 0, s_side>>>();
    scan2_k <<<1, 64, 0, s_side>>>();
    scan3_k <<<(N_NODES + 255) / 256, 256, 0, s_side>>>();
    fill_k  <<<(N_EDGES + 255) / 256, 256, 0, s_side>>>(src, dst);
    cudaEventRecord(ev_join, s_side);

    // main stream: pure gemm1 runs concurrently with CSR build
    gemm_k<<<gemm_blocks, 256>>>(h, W1, pHW);

    // join, then the serial tail
    cudaStreamWaitEvent(0, ev_join, 0);
    gather_t<true> <<<gath_blocks, 256>>>(pHW, b1, pB);   // bufB = relu(.)·ns
    gemm_k<<<gemm_blocks, 256>>>(pB, W2, pHW);
    gather_t<false><<<gath_blocks, 256>>>(pHW, b2, pC);   // bufC = h2
    head_k<<<N_GRAPHS, 128>>>(pC, gid, Wc1, bc1, Wc2, bc2, Wc3, bc3, out);
}